// round 16
// baseline (speedup 1.0000x reference)
#include <cuda_runtime.h>
#include <math.h>

#define Bb   4
#define Hh   12
#define Nn   2048
#define Mm   512
#define Dd   64
#define DIMc 768
#define SCALEc 0.125f
#define NEGc  (-1e9f)

#define O1_OFF 0
#define O2_OFF 6291456
#define O3_OFF 7864320
#define O4_OFF 7867392

#define MASK_ELEMS 50331648  // B*H*N*M

// ---------------- f32x2 helpers --------------------------------------------
typedef unsigned long long ull;

__device__ __forceinline__ ull pack2s(float a) {          // (a, a)
    ull r;
    asm("mov.b64 %0, {%1, %1};" : "=l"(r) : "f"(a));
    return r;
}
__device__ __forceinline__ ull pack2(float a, float b) {
    ull r;
    asm("mov.b64 %0, {%1, %2};" : "=l"(r) : "f"(a), "f"(b));
    return r;
}
__device__ __forceinline__ void unpack2(ull v, float& lo, float& hi) {
    asm("mov.b64 {%0, %1}, %2;" : "=f"(lo), "=f"(hi) : "l"(v));
}
#define FMA2(acc, a, b) asm("fma.rn.f32x2 %0, %1, %2, %0;" : "+l"(acc) : "l"(a), "l"(b))
#define MUL2(acc, a)    asm("mul.rn.f32x2 %0, %0, %1;" : "+l"(acc) : "l"(a))

#define CP16(dst, src, pred) \
    asm volatile("cp.async.ca.shared.global [%0], [%1], 16, %2;" \
                 :: "r"(dst), "l"(src), "r"(pred))
#define CP_COMMIT() asm volatile("cp.async.commit_group;")
#define CP_WAIT1()  asm volatile("cp.async.wait_group 1;")
#define CP_WAIT0()  asm volatile("cp.async.wait_group 0;")

// ---------------- scratch (device globals; no allocation allowed) ----------
__device__ float g_tq[Bb*Hh*Nn*Dd];
__device__ float g_tk[Bb*Hh*Nn*Dd];
__device__ float g_tv[Bb*Hh*Nn*Dd];
__device__ float g_kq[Bb*Hh*Mm*Dd];
__device__ float g_kk[Bb*Hh*Mm*Dd];
__device__ float g_kv[Bb*Hh*Mm*Dd];
__device__ float g_cq[Bb*Hh*Dd];
__device__ float g_cdk[Bb*Hh*Dd];
__device__ float g_cdv[Bb*Hh*Dd];
__device__ float g_att[Bb*Hh*Nn*Dd];
__device__ float g_kout[Bb*Hh*Mm*Dd];
__device__ float g_cout[Bb*DIMc];
__device__ unsigned char g_mask[MASK_ELEMS];
__device__ int g_mode;

// ---------------- mask dtype sniffing + normalization ----------------------
__global__ void detect_mask_kernel(const void* m) {
    const unsigned int* w = (const unsigned int*)m;
    __shared__ int notint, notf32;
    if (threadIdx.x == 0) { notint = 0; notf32 = 0; }
    __syncthreads();
    for (int i = threadIdx.x; i < 1024; i += blockDim.x) {
        unsigned int v = w[i];
        if (v > 1u) notint = 1;
        if (v != 0u && v != 0x3F800000u) notf32 = 1;
    }
    __syncthreads();
    if (threadIdx.x == 0) g_mode = notint ? (notf32 ? 2 : 1) : 0;
}

__global__ void norm_mask_kernel(const void* m) {
    int gid = blockIdx.x * blockDim.x + threadIdx.x;
    if (gid * 4 >= MASK_ELEMS) return;
    int mode = g_mode;
    uchar4 r;
    int base = gid * 4;
    if (mode == 0) {
        const int* p = (const int*)m;
        r.x = p[base+0] != 0; r.y = p[base+1] != 0;
        r.z = p[base+2] != 0; r.w = p[base+3] != 0;
    } else if (mode == 1) {
        const float* p = (const float*)m;
        r.x = p[base+0] != 0.f; r.y = p[base+1] != 0.f;
        r.z = p[base+2] != 0.f; r.w = p[base+3] != 0.f;
    } else {
        const unsigned char* p = (const unsigned char*)m;
        r.x = p[base+0] != 0; r.y = p[base+1] != 0;
        r.z = p[base+2] != 0; r.w = p[base+3] != 0;
    }
    ((uchar4*)g_mask)[gid] = r;
}

// ---------------- merged QKV projection GEMM (x | kx | clst in one grid) ----
#define AST 20   // A smem row stride (floats)
#define BST 132  // B smem row stride

__global__ __launch_bounds__(512, 2) void gemm_qkv_kernel(
    const float* __restrict__ x_in, const float* __restrict__ kx_in,
    const float* __restrict__ clst_in, const float* __restrict__ W)
{
    __shared__ float As[2][128 * AST];
    __shared__ float Bs[2][16 * BST];
    int by = blockIdx.y;
    const float* X;
    int rows, L, which, m0;
    if (by < 64)      { X = x_in;    rows = 8192; L = 2048; which = 0; m0 = by * 128; }
    else if (by < 80) { X = kx_in;   rows = 2048; L = 512;  which = 1; m0 = (by - 64) * 128; }
    else              { X = clst_in; rows = 4;    L = 1;    which = 2; m0 = 0; }
    int c0 = blockIdx.x * 128;
    int tid = threadIdx.x, tx = tid & 15, ty = tid >> 4;   // ty 0..31

    ull acc[4][4];
#pragma unroll
    for (int r = 0; r < 4; r++)
#pragma unroll
        for (int c = 0; c < 4; c++) acc[r][c] = 0ull;

    unsigned asm_base[2], bsm_base[2];
#pragma unroll
    for (int s = 0; s < 2; s++) {
        asm_base[s] = (unsigned)__cvta_generic_to_shared(&As[s][0]);
        bsm_base[s] = (unsigned)__cvta_generic_to_shared(&Bs[s][0]);
    }

#define ISSUE_QKV(t, s) do {                                                 \
        int k0_ = (t) * 16;                                                  \
        { int m_ = tid >> 2, kc = tid & 3;                                   \
          const float* src = X + (size_t)(m0 + m_) * 768 + k0_ + kc * 4;     \
          int pred = (m0 + m_ < rows) ? 16 : 0;                              \
          CP16(asm_base[s] + (m_ * AST + kc * 4) * 4, src, pred); }          \
        { int k_ = tid >> 5, cc = tid & 31;                                  \
          const float* src = W + (size_t)(k0_ + k_) * 2304 + c0 + cc * 4;    \
          CP16(bsm_base[s] + (k_ * BST + cc * 4) * 4, src, 16); }            \
        CP_COMMIT();                                                         \
    } while (0)

    ISSUE_QKV(0, 0);
    for (int t = 0; t < 48; t++) {
        int cur = t & 1;
        if (t < 47) { ISSUE_QKV(t + 1, cur ^ 1); CP_WAIT1(); }
        else CP_WAIT0();
        __syncthreads();
        const float* A_ = &As[cur][0];
        const float* B_ = &Bs[cur][0];
#pragma unroll
        for (int kq = 0; kq < 4; kq++) {
            float4 a4[4];
#pragma unroll
            for (int r = 0; r < 4; r++)
                a4[r] = *(const float4*)(A_ + (ty * 4 + r) * AST + kq * 4);
#pragma unroll
            for (int dk = 0; dk < 4; dk++) {
                int k = kq * 4 + dk;
                ulonglong2 b0 = *(const ulonglong2*)(B_ + k * BST + tx * 4);
                ulonglong2 b1 = *(const ulonglong2*)(B_ + k * BST + 64 + tx * 4);
#pragma unroll
                for (int r = 0; r < 4; r++) {
                    float av = (dk == 0) ? a4[r].x : (dk == 1) ? a4[r].y
                             : (dk == 2) ? a4[r].z : a4[r].w;
                    ull ap = pack2s(av);
                    FMA2(acc[r][0], ap, b0.x);
                    FMA2(acc[r][1], ap, b0.y);
                    FMA2(acc[r][2], ap, b1.x);
                    FMA2(acc[r][3], ap, b1.y);
                }
            }
        }
        __syncthreads();
    }
#undef ISSUE_QKV

    float* dq = (which == 0) ? g_tq : (which == 1) ? g_kq : g_cq;
    float* dk_ = (which == 0) ? g_tk : (which == 1) ? g_kk : g_cdk;
    float* dv = (which == 0) ? g_tv : (which == 1) ? g_kv : g_cdv;
#pragma unroll
    for (int r = 0; r < 4; r++) {
        int row = m0 + ty * 4 + r;
        if (row >= rows) continue;
        int b = row / L, n = row % L;
#pragma unroll
        for (int c2 = 0; c2 < 4; c2++) {
            float v0, v1;
            unpack2(acc[r][c2], v0, v1);
#pragma unroll
            for (int u = 0; u < 2; u++) {
                int col = c0 + ((c2 >= 2) ? 64 : 0) + tx * 4 + (c2 & 1) * 2 + u;
                float v = u ? v1 : v0;
                int s = col / 768;
                int rem = col - s * 768;
                int h = rem >> 6, d = rem & 63;
                float* dst = (s == 0) ? dq : (s == 1) ? dk_ : dv;
                dst[((b * Hh + h) * L + n) * Dd + d] = v;
            }
        }
    }
}

// ---------------- merged output projection GEMM (o1 | o2 in one grid) -------
__global__ __launch_bounds__(512, 2) void gemm_proj_kernel(
    const float* __restrict__ W, const float* __restrict__ bias,
    float* __restrict__ o1, float* __restrict__ o2)
{
    __shared__ float As[2][128 * AST];
    __shared__ float Bs[2][16 * BST];
    int by = blockIdx.y;
    const float* A;
    float* O;
    int rows, L, m0;
    if (by < 64) { A = g_att;  O = o1; rows = 8192; L = 2048; m0 = by * 128; }
    else         { A = g_kout; O = o2; rows = 2048; L = 512;  m0 = (by - 64) * 128; }
    int c0 = blockIdx.x * 128;
    int tid = threadIdx.x, tx = tid & 15, ty = tid >> 4;

    ull acc[4][4];
#pragma unroll
    for (int r = 0; r < 4; r++)
#pragma unroll
        for (int c = 0; c < 4; c++) acc[r][c] = 0ull;

    unsigned asm_base[2], bsm_base[2];
#pragma unroll
    for (int s = 0; s < 2; s++) {
        asm_base[s] = (unsigned)__cvta_generic_to_shared(&As[s][0]);
        bsm_base[s] = (unsigned)__cvta_generic_to_shared(&Bs[s][0]);
    }

#define ISSUE_PRJ(t, s) do {                                                  \
        int k0_ = (t) * 16;                                                   \
        { int m_ = tid >> 2, kc = tid & 3;                                    \
          int row = m0 + m_, kg = k0_ + kc * 4;                               \
          int b_ = row / L, n_ = row % L;                                     \
          int h_ = kg >> 6, d_ = kg & 63;                                     \
          const float* src = A + ((size_t)(b_ * Hh + h_) * L + n_) * 64 + d_; \
          CP16(asm_base[s] + (m_ * AST + kc * 4) * 4, src, 16); }             \
        { int k_ = tid >> 5, cc = tid & 31;                                   \
          const float* src = W + (size_t)(k0_ + k_) * 768 + c0 + cc * 4;      \
          CP16(bsm_base[s] + (k_ * BST + cc * 4) * 4, src, 16); }             \
        CP_COMMIT();                                                          \
    } while (0)

    ISSUE_PRJ(0, 0);
    for (int t = 0; t < 48; t++) {
        int cur = t & 1;
        if (t < 47) { ISSUE_PRJ(t + 1, cur ^ 1); CP_WAIT1(); }
        else CP_WAIT0();
        __syncthreads();
        const float* A_ = &As[cur][0];
        const float* B_ = &Bs[cur][0];
#pragma unroll
        for (int kq = 0; kq < 4; kq++) {
            float4 a4[4];
#pragma unroll
            for (int r = 0; r < 4; r++)
                a4[r] = *(const float4*)(A_ + (ty * 4 + r) * AST + kq * 4);
#pragma unroll
            for (int dk = 0; dk < 4; dk++) {
                int k = kq * 4 + dk;
                ulonglong2 b0 = *(const ulonglong2*)(B_ + k * BST + tx * 4);
                ulonglong2 b1 = *(const ulonglong2*)(B_ + k * BST + 64 + tx * 4);
#pragma unroll
                for (int r = 0; r < 4; r++) {
                    float av = (dk == 0) ? a4[r].x : (dk == 1) ? a4[r].y
                             : (dk == 2) ? a4[r].z : a4[r].w;
                    ull ap = pack2s(av);
                    FMA2(acc[r][0], ap, b0.x);
                    FMA2(acc[r][1], ap, b0.y);
                    FMA2(acc[r][2], ap, b1.x);
                    FMA2(acc[r][3], ap, b1.y);
                }
            }
        }
        __syncthreads();
    }
#undef ISSUE_PRJ

#pragma unroll
    for (int r = 0; r < 4; r++) {
        int row = m0 + ty * 4 + r;
#pragma unroll
        for (int c2 = 0; c2 < 4; c2++) {
            float v0, v1;
            unpack2(acc[r][c2], v0, v1);
            int col = c0 + ((c2 >= 2) ? 64 : 0) + tx * 4 + (c2 & 1) * 2;
            O[row * 768 + col]     = v0 + bias[col];
            O[row * 768 + col + 1] = v1 + bias[col + 1];
        }
    }
}

// ---------------- branch 1 (256 thr x 2 CTA/SM, i-tile 32, 1i x 8j tiles) ---
// smem: QsT 64x34 ([k][i]) | KT 64x68 (phase A [d][j]; phase C KV [j][d]) |
//       Ps 64x34 ([j][i]) | dots 32x514 | rs1,rs2
__global__ __launch_bounds__(256, 2) void branch1_kernel(
    const float* __restrict__ krd, float* __restrict__ o4)
{
    extern __shared__ float sm[];
    float* QsT  = sm;                 // 64*34
    float* KT   = QsT + 64 * 34;      // 64*68
    float* Ps   = KT + 64 * 68;       // 64*34
    float* dots = Ps + 64 * 34;       // 32*514
    float* rs1  = dots + 32 * 514;    // 32
    float* rs2  = rs1 + 32;           // 32

    int bh = blockIdx.y;
    int i0 = blockIdx.x * 32;
    int tid = threadIdx.x;
    int w = tid >> 5, lane = tid & 31;                      // 8 warps
    int iQ = tid >> 3, jq = (tid & 7) * 8;                  // 1i x 8j tile

    int pd = tid & 63, pj = tid >> 6;   // pj 0..3 (tile load coords)

    for (int li = tid; li < 2048; li += 256) {
        int d = li & 63, i = li >> 6;
        QsT[d * 34 + i] = g_tq[(bh * Nn + i0 + i) * Dd + d];
    }

    // ---- phase A: dots = Q @ K^T * scale, K tiles reg-prefetched ----
    float pf[16];
#pragma unroll
    for (int q = 0; q < 16; q++)
        pf[q] = g_kk[(bh * Mm + (pj + q * 4)) * Dd + pd];

    for (int jt = 0; jt < 8; jt++) {
        int j0 = jt * 64;
        __syncthreads();
#pragma unroll
        for (int q = 0; q < 16; q++)
            KT[pd * 68 + pj + q * 4] = pf[q];
        __syncthreads();
        if (jt < 7) {
#pragma unroll
            for (int q = 0; q < 16; q++)
                pf[q] = g_kk[(bh * Mm + j0 + 64 + pj + q * 4) * Dd + pd];
        }
        ull acc[4];
        acc[0] = acc[1] = acc[2] = acc[3] = 0ull;
#pragma unroll 16
        for (int k = 0; k < 64; k++) {
            ull ap = pack2s(QsT[k * 34 + iQ]);
            const float* bp = KT + k * 68 + jq;
            ulonglong2 B0 = *(const ulonglong2*)(bp);
            ulonglong2 B1 = *(const ulonglong2*)(bp + 4);
            FMA2(acc[0], ap, B0.x); FMA2(acc[1], ap, B0.y);
            FMA2(acc[2], ap, B1.x); FMA2(acc[3], ap, B1.y);
        }
        {
            float* dp = dots + iQ * 514 + j0 + jq;
#pragma unroll
            for (int c = 0; c < 4; c++) {
                float v0, v1;
                unpack2(acc[c], v0, v1);
                *(float2*)(dp + c * 2) = make_float2(v0 * SCALEc, v1 * SCALEc);
            }
        }
    }
    __syncthreads();

    // ---- row stats with fused mask (8 warps x 4 rows = 32) -----------------
    for (int r = 0; r < 4; r++) {
        int i = w * 4 + r;
        const unsigned char* mrow = g_mask + (size_t)(bh * Nn + i0 + i) * Mm;
        float mx = -INFINITY;
        for (int j2 = lane * 2; j2 < 512; j2 += 64) {
            ull dv = *(const ull*)(dots + i * 514 + j2);
            float lo, hi;
            unpack2(dv, lo, hi);
            unsigned short mv = *(const unsigned short*)(mrow + j2);
            if (mv & 0xFFu) lo = NEGc;
            if (mv >> 8)    hi = NEGc;
            *(ull*)(dots + i * 514 + j2) = pack2(lo, hi);
            mx = fmaxf(mx, fmaxf(lo, hi));
        }
#pragma unroll
        for (int o = 16; o; o >>= 1) mx = fmaxf(mx, __shfl_xor_sync(0xffffffffu, mx, o));
        float s1 = 0.f, s2 = 0.f;
        for (int j2 = lane * 2; j2 < 512; j2 += 64) {
            ull dv = *(const ull*)(dots + i * 514 + j2);
            float lo, hi;
            unpack2(dv, lo, hi);
            float e0 = __expf(lo - mx), e1 = __expf(hi - mx);
            ull ep = pack2(e0, e1);
            ull e2p = ep;  MUL2(e2p, e2p);
            ull e4p = e2p; MUL2(e4p, e4p);
            ull e8p = e4p; MUL2(e8p, e8p);
            ull e16p = e8p; MUL2(e16p, e16p);
            ull e24p = e16p; MUL2(e24p, e8p);
            float f24a, f24b;
            unpack2(e24p, f24a, f24b);
            s1 += e0 + e1;
            s2 += f24a + f24b;
            *(ull*)(dots + i * 514 + j2) = ep;
        }
#pragma unroll
        for (int o = 16; o; o >>= 1) {
            s1 += __shfl_xor_sync(0xffffffffu, s1, o);
            s2 += __shfl_xor_sync(0xffffffffu, s2, o);
        }
        if (lane == 0) { rs1[i] = 1.f / s1; rs2[i] = 1.f / s2; }
    }

    // ---- phase C: attn_hot out + P build, PV accumulate (KV prefetched) ---
    float* KV = KT;   // [j][d] stride 68
    ull acc2[4];
    acc2[0] = acc2[1] = acc2[2] = acc2[3] = 0ull;

    float pfc[16];
#pragma unroll
    for (int q = 0; q < 16; q++)
        pfc[q] = g_kv[(bh * Mm + (pj + q * 4)) * Dd + pd];

    for (int jt = 0; jt < 8; jt++) {
        int j0 = jt * 64;
        __syncthreads();
#pragma unroll
        for (int q = 0; q < 16; q++)
            KV[(pj + q * 4) * 68 + pd] = pfc[q];
        if (jt < 7) {
#pragma unroll
            for (int q = 0; q < 16; q++)
                pfc[q] = g_kv[(bh * Mm + j0 + 64 + pj + q * 4) * Dd + pd];
        }
        for (int idx2 = tid; idx2 < 1024; idx2 += 256) {
            int jj = idx2 >> 4, ii2 = (idx2 & 15) * 2;
            float e0 = dots[ii2 * 514 + j0 + jj];
            float e1 = dots[(ii2 + 1) * 514 + j0 + jj];
            ull ep = pack2(e0, e1);
            ull e2p = ep;  MUL2(e2p, e2p);
            ull e4p = e2p; MUL2(e4p, e4p);
            ull e8p = e4p; MUL2(e8p, e8p);
            ull e16p = e8p; MUL2(e16p, e16p);
            ull e24p = e16p; MUL2(e24p, e8p);
            int gi = (bh * Mm + j0 + jj) * Nn + i0 + ii2;
            ull krp = *(const ull*)(krd + gi);
            float k0f, k1f;
            unpack2(krp, k0f, k1f);
            float e24a, e24b;
            unpack2(e24p, e24a, e24b);
            *(float2*)(o4 + gi) = make_float2(e24a * rs2[ii2] * k0f,
                                              e24b * rs2[ii2 + 1] * k1f);
            *(float2*)(Ps + jj * 34 + ii2) = make_float2(e0 * rs1[ii2] * k0f,
                                                         e1 * rs1[ii2 + 1] * k1f);
        }
        __syncthreads();
#pragma unroll 16
        for (int k = 0; k < 64; k++) {
            ull ap = pack2s(Ps[k * 34 + iQ]);
            const float* bp = KV + k * 68 + jq;
            ulonglong2 B0 = *(const ulonglong2*)(bp);
            ulonglong2 B1 = *(const ulonglong2*)(bp + 4);
            FMA2(acc2[0], ap, B0.x); FMA2(acc2[1], ap, B0.y);
            FMA2(acc2[2], ap, B1.x); FMA2(acc2[3], ap, B1.y);
        }
    }
    {
        float v[8];
#pragma unroll
        for (int c = 0; c < 4; c++) unpack2(acc2[c], v[c * 2], v[c * 2 + 1]);
        float* op = g_att + (bh * Nn + i0 + iQ) * Dd + jq;
        *(float4*)(op)     = make_float4(v[0], v[1], v[2], v[3]);
        *(float4*)(op + 4) = make_float4(v[4], v[5], v[6], v[7]);
    }
}

// ---------------- branch 2 (512 thr x 2 CTA/SM): k_q vs t_k, 1i x 8j --------
__global__ __launch_bounds__(512, 2) void branch2_kernel(const float* __restrict__ krd)
{
    extern __shared__ float sm[];
    float* QsT = sm;                 // 64*68 [d][i]
    float* KsT = QsT + 64 * 68;      // 64*68 [d][j]
    float* Vs  = KsT + 64 * 68;      // 64*68 [j][d]
    float* Ss  = Vs + 64 * 68;       // 64*66 [i][j]
    float* Ps  = Ss + 64 * 66;       // 64*66 [j][i]
    float* mxA = Ps + 64 * 66;       // 64
    float* dnA = mxA + 64;           // 64
    float* fsc = dnA + 64;           // 64

    int bh = blockIdx.y;
    int i0 = blockIdx.x * 64;
    int tid = threadIdx.x;
    int w = tid >> 5, lane = tid & 31;
    int iQ = tid >> 3, jq = (tid & 7) * 8;   // iQ 0..63, jq 0..56

    for (int li = tid; li < 4096; li += 512) {
        int d = li & 63, i = li >> 6;
        QsT[d * 68 + i] = g_kq[(bh * Mm + i0 + i) * Dd + d];
    }
    if (tid < 64) { mxA[tid] = -INFINITY; dnA[tid] = 0.f; }

    ull acc[4];
    acc[0] = acc[1] = acc[2] = acc[3] = 0ull;

    for (int nt = 0; nt < 32; nt++) {
        int n0 = nt * 64;
        __syncthreads();
        for (int li = tid; li < 4096; li += 512) {
            int d = li & 63, j = li >> 6;
            KsT[d * 68 + j] = g_tk[(bh * Nn + n0 + j) * Dd + d];
            Vs[j * 68 + d]  = g_tv[(bh * Nn + n0 + j) * Dd + d];
        }
        __syncthreads();
        // S = Q @ K^T * scale
        {
            ull sac[4];
            sac[0] = sac[1] = sac[2] = sac[3] = 0ull;
#pragma unroll 16
            for (int k = 0; k < 64; k++) {
                ull ap = pack2s(QsT[k * 68 + iQ]);
                const float* bp = KsT + k * 68 + jq;
                ulonglong2 B0 = *(const ulonglong2*)(bp);
                ulonglong2 B1 = *(const ulonglong2*)(bp + 4);
                FMA2(sac[0], ap, B0.x); FMA2(sac[1], ap, B0.y);
                FMA2(sac[2], ap, B1.x); FMA2(sac[3], ap, B1.y);
            }
            float* sp = Ss + iQ * 66 + jq;
#pragma unroll
            for (int c = 0; c < 4; c++) {
                float v0, v1;
                unpack2(sac[c], v0, v1);
                *(float2*)(sp + c * 2) = make_float2(v0 * SCALEc, v1 * SCALEc);
            }
        }
        __syncthreads();
        // mask (transposed att_mask; coalesced over ii)
        for (int idx = tid; idx < 4096; idx += 512) {
            int jj = idx >> 6, ii = idx & 63;
            if (g_mask[(bh * Nn + n0 + jj) * Mm + i0 + ii]) Ss[ii * 66 + jj] = NEGc;
        }
        __syncthreads();
        // online softmax stats (each warp 4 rows); store e in Ss
        for (int r = 0; r < 4; r++) {
            int i = w * 4 + r;
            int j2 = lane * 2;
            ull sv = *(const ull*)(Ss + i * 66 + j2);
            float lo, hi;
            unpack2(sv, lo, hi);
            float tmx = fmaxf(lo, hi);
#pragma unroll
            for (int o = 16; o; o >>= 1) tmx = fmaxf(tmx, __shfl_xor_sync(0xffffffffu, tmx, o));
            float om = mxA[i];
            float nm = fmaxf(om, tmx);
            float e0 = __expf(lo - nm), e1 = __expf(hi - nm);
            *(ull*)(Ss + i * 66 + j2) = pack2(e0, e1);
            float s = e0 + e1;
#pragma unroll
            for (int o = 16; o; o >>= 1) s += __shfl_xor_sync(0xffffffffu, s, o);
            if (lane == 0) {
                float f = __expf(om - nm);
                dnA[i] = dnA[i] * f + s;
                mxA[i] = nm;
                fsc[i] = f;
            }
        }
        __syncthreads();
        // P = e * krd (coalesced over jj)
        for (int idx = tid; idx < 4096; idx += 512) {
            int ii = idx >> 6, jj = idx & 63;
            float kr = krd[(bh * Mm + i0 + ii) * Nn + n0 + jj];
            Ps[jj * 66 + ii] = Ss[ii * 66 + jj] * kr;
        }
        __syncthreads();
        // rescale + accumulate P @ V  (1i x 8d)
        {
            ull fp = pack2s(fsc[iQ]);
            MUL2(acc[0], fp); MUL2(acc[1], fp);
            MUL2(acc[2], fp); MUL2(acc[3], fp);
        }
#pragma unroll 16
        for (int k = 0; k < 64; k++) {
            ull ap = pack2s(Ps[k * 66 + iQ]);
            const float* bp = Vs + k * 68 + jq;
            ulonglong2 B0 = *(const ulonglong2*)(bp);
            ulonglong2 B1 = *(const ulonglong2*)(bp + 4);
            FMA2(acc[0], ap, B0.x); FMA2(acc[1], ap, B0.y);
            FMA2(acc[2], ap, B1.x); FMA2(acc[3], ap, B1.y);
        }
    }
    __syncthreads();
    {
        float inv = 1.f / dnA[iQ];
        float v[8];
#pragma unroll
        for (int c = 0; c < 4; c++) unpack2(acc[c], v[c * 2], v[c * 2 + 1]);
        float* op = g_kout + (bh * Mm + i0 + iQ) * Dd + jq;
        *(float4*)(op)     = make_float4(v[0] * inv, v[1] * inv, v[2] * inv, v[3] * inv);
        *(float4*)(op + 4) = make_float4(v[4] * inv, v[5] * inv, v[6] * inv, v[7] * inv);
    }
}

// ---------------- branch 3: cluster query (1 per b,h) -----------------------
__global__ __launch_bounds__(256) void branch3_kernel()
{
    __shared__ float cq[64];
    __shared__ float pb[512];
    __shared__ float red[8];
    __shared__ float outp[256];
    __shared__ float smax, ssum;
    int bh = blockIdx.x;
    int b = bh / Hh, h = bh % Hh;
    int tid = threadIdx.x, w = tid >> 5, lane = tid & 31;

    if (tid < 64) cq[tid] = g_cq[bh * Dd + tid];
    __syncthreads();

    for (int j = tid; j < 512; j += 256) {
        float s = 0.f;
#pragma unroll 16
        for (int d = 0; d < 64; d++) s = fmaf(cq[d], g_kk[(bh * Mm + j) * Dd + d], s);
        s *= SCALEc;
        if (g_mask[(size_t)(bh * Nn) * Mm + j]) s = NEGc;
        pb[j] = s;
    }
    __syncthreads();
    float m = -INFINITY;
    for (int j = tid; j < 512; j += 256) m = fmaxf(m, pb[j]);
#pragma unroll
    for (int o = 16; o; o >>= 1) m = fmaxf(m, __shfl_xor_sync(0xffffffffu, m, o));
    if (lane == 0) red[w] = m;
    __syncthreads();
    if (tid == 0) {
        float mm = red[0];
        for (int i = 1; i < 8; i++) mm = fmaxf(mm, red[i]);
        smax = mm;
    }
    __syncthreads();
    float sum = 0.f;
    for (int j = tid; j < 512; j += 256) {
        float e = __expf(pb[j] - smax);
        pb[j] = e;
        sum += e;
    }
#pragma unroll
    for (int o = 16; o; o >>= 1) sum += __shfl_xor_sync(0xffffffffu, sum, o);
    if (lane == 0) red[w] = sum;
    __syncthreads();
    if (tid == 0) {
        float s = 0.f;
        for (int i = 0; i < 8; i++) s += red[i];
        ssum = s;
    }
    __syncthreads();
    int d = tid & 63, q = tid >> 6;
    float a = 0.f;
    for (int j = q * 128; j < (q + 1) * 128; j++)
        a = fmaf(pb[j], g_kv[(bh * Mm + j) * Dd + d], a);
    outp[q * 64 + d] = a;
    __syncthreads();
    if (tid < 64) {
        float tot = outp[tid] + outp[64 + tid] + outp[128 + tid] + outp[192 + tid];
        g_cout[b * DIMc + h * Dd + tid] = tot / ssum;
    }
}

// ---------------- cluster projection ----------------------------------------
__global__ __launch_bounds__(256) void cproj_kernel(
    const float* __restrict__ W, const float* __restrict__ bias,
    float* __restrict__ o3)
{
    int gid = blockIdx.x * 256 + threadIdx.x;  // 3072 total
    int b = gid / 768, c = gid % 768;
    float a = bias[c];
    for (int k = 0; k < 768; k++) a = fmaf(g_cout[b * 768 + k], W[k * 768 + c], a);
    o3[gid] = a;
}

// ---------------- launch ----------------------------------------------------
extern "C" void kernel_launch(void* const* d_in, const int* in_sizes, int n_in,
                              void* d_out, int out_size) {
    const float* x    = (const float*)d_in[0];
    const float* kx   = (const float*)d_in[1];
    const float* krd  = (const float*)d_in[2];
    const float* clst = (const float*)d_in[3];
    const void*  amsk = d_in[4];
    const float* Wqkv = (const float*)d_in[5];
    const float* Wout = (const float*)d_in[6];
    const float* bout = (const float*)d_in[7];
    float* out = (float*)d_out;

    float* o1 = out + O1_OFF;
    float* o2 = out + O2_OFF;
    float* o3 = out + O3_OFF;
    float* o4 = out + O4_OFF;

    size_t sm1 = (size_t)(64*34 + 64*68 + 64*34 + 32*514 + 64) * 4;      // 101,376 B
    size_t sm2 = (size_t)(64*68*3 + 64*66*2 + 192) * 4;                  //  86,784 B
    cudaFuncSetAttribute(branch1_kernel, cudaFuncAttributeMaxDynamicSharedMemorySize, (int)sm1);
    cudaFuncSetAttribute(branch2_kernel, cudaFuncAttributeMaxDynamicSharedMemorySize, (int)sm2);

    detect_mask_kernel<<<1, 256>>>(amsk);
    norm_mask_kernel<<<MASK_ELEMS / 4 / 256, 256>>>(amsk);

    // merged QKV projection (x | kx | clst)
    gemm_qkv_kernel<<<dim3(18, 81), 512>>>(x, kx, clst, Wqkv);

    // attention branches
    branch1_kernel<<<dim3(64, 48), 256, sm1>>>(krd, o4);
    branch2_kernel<<<dim3(8,  48), 512, sm2>>>(krd);
    branch3_kernel<<<48, 256>>>();

    // merged output projections (o1 | o2)
    gemm_proj_kernel<<<dim3(6, 80), 512>>>(Wout, bout, o1, o2);
    cproj_kernel<<<12, 256>>>(Wout, bout, o3);
}

// round 17
// speedup vs baseline: 1.5804x; 1.5804x over previous
#include <cuda_runtime.h>
#include <math.h>

#define Bb   4
#define Hh   12
#define Nn   2048
#define Mm   512
#define Dd   64
#define DIMc 768
#define SCALEc 0.125f
#define NEGc  (-1e9f)

#define O1_OFF 0
#define O2_OFF 6291456
#define O3_OFF 7864320
#define O4_OFF 7867392

#define MASK_ELEMS 50331648  // B*H*N*M

// ---------------- f32x2 helpers --------------------------------------------
typedef unsigned long long ull;

__device__ __forceinline__ ull pack2s(float a) {          // (a, a)
    ull r;
    asm("mov.b64 %0, {%1, %1};" : "=l"(r) : "f"(a));
    return r;
}
__device__ __forceinline__ ull pack2(float a, float b) {
    ull r;
    asm("mov.b64 %0, {%1, %2};" : "=l"(r) : "f"(a), "f"(b));
    return r;
}
__device__ __forceinline__ void unpack2(ull v, float& lo, float& hi) {
    asm("mov.b64 {%0, %1}, %2;" : "=f"(lo), "=f"(hi) : "l"(v));
}
#define FMA2(acc, a, b) asm("fma.rn.f32x2 %0, %1, %2, %0;" : "+l"(acc) : "l"(a), "l"(b))
#define MUL2(acc, a)    asm("mul.rn.f32x2 %0, %0, %1;" : "+l"(acc) : "l"(a))

#define CP16(dst, src, pred) \
    asm volatile("cp.async.ca.shared.global [%0], [%1], 16, %2;" \
                 :: "r"(dst), "l"(src), "r"(pred))
#define CP_COMMIT() asm volatile("cp.async.commit_group;")
#define CP_WAIT1()  asm volatile("cp.async.wait_group 1;")
#define CP_WAIT0()  asm volatile("cp.async.wait_group 0;")

// ---------------- scratch (device globals; no allocation allowed) ----------
__device__ float g_tq[Bb*Hh*Nn*Dd];
__device__ float g_tk[Bb*Hh*Nn*Dd];
__device__ float g_tv[Bb*Hh*Nn*Dd];
__device__ float g_kq[Bb*Hh*Mm*Dd];
__device__ float g_kk[Bb*Hh*Mm*Dd];
__device__ float g_kv[Bb*Hh*Mm*Dd];
__device__ float g_cq[Bb*Hh*Dd];
__device__ float g_cdk[Bb*Hh*Dd];
__device__ float g_cdv[Bb*Hh*Dd];
__device__ float g_att[Bb*Hh*Nn*Dd];
__device__ float g_kout[Bb*Hh*Mm*Dd];
__device__ float g_cout[Bb*DIMc];
__device__ unsigned char g_mask[MASK_ELEMS];
__device__ int g_mode;

// ---------------- mask dtype sniffing + normalization ----------------------
__global__ void detect_mask_kernel(const void* m) {
    const unsigned int* w = (const unsigned int*)m;
    __shared__ int notint, notf32;
    if (threadIdx.x == 0) { notint = 0; notf32 = 0; }
    __syncthreads();
    for (int i = threadIdx.x; i < 1024; i += blockDim.x) {
        unsigned int v = w[i];
        if (v > 1u) notint = 1;
        if (v != 0u && v != 0x3F800000u) notf32 = 1;
    }
    __syncthreads();
    if (threadIdx.x == 0) g_mode = notint ? (notf32 ? 2 : 1) : 0;
}

__global__ void norm_mask_kernel(const void* m) {
    int gid = blockIdx.x * blockDim.x + threadIdx.x;
    if (gid * 4 >= MASK_ELEMS) return;
    int mode = g_mode;
    uchar4 r;
    int base = gid * 4;
    if (mode == 0) {
        const int* p = (const int*)m;
        r.x = p[base+0] != 0; r.y = p[base+1] != 0;
        r.z = p[base+2] != 0; r.w = p[base+3] != 0;
    } else if (mode == 1) {
        const float* p = (const float*)m;
        r.x = p[base+0] != 0.f; r.y = p[base+1] != 0.f;
        r.z = p[base+2] != 0.f; r.w = p[base+3] != 0.f;
    } else {
        const unsigned char* p = (const unsigned char*)m;
        r.x = p[base+0] != 0; r.y = p[base+1] != 0;
        r.z = p[base+2] != 0; r.w = p[base+3] != 0;
    }
    ((uchar4*)g_mask)[gid] = r;
}

// ---------------- merged QKV projection GEMM (x | kx | clst in one grid) ----
#define AST 20   // A smem row stride (floats)
#define BST 132  // B smem row stride

__global__ __launch_bounds__(512, 2) void gemm_qkv_kernel(
    const float* __restrict__ x_in, const float* __restrict__ kx_in,
    const float* __restrict__ clst_in, const float* __restrict__ W)
{
    __shared__ float As[2][128 * AST];
    __shared__ float Bs[2][16 * BST];
    int by = blockIdx.y;
    const float* X;
    int rows, L, which, m0;
    if (by < 64)      { X = x_in;    rows = 8192; L = 2048; which = 0; m0 = by * 128; }
    else if (by < 80) { X = kx_in;   rows = 2048; L = 512;  which = 1; m0 = (by - 64) * 128; }
    else              { X = clst_in; rows = 4;    L = 1;    which = 2; m0 = 0; }
    int c0 = blockIdx.x * 128;
    int tid = threadIdx.x, tx = tid & 15, ty = tid >> 4;   // ty 0..31

    ull acc[4][4];
#pragma unroll
    for (int r = 0; r < 4; r++)
#pragma unroll
        for (int c = 0; c < 4; c++) acc[r][c] = 0ull;

    unsigned asm_base[2], bsm_base[2];
#pragma unroll
    for (int s = 0; s < 2; s++) {
        asm_base[s] = (unsigned)__cvta_generic_to_shared(&As[s][0]);
        bsm_base[s] = (unsigned)__cvta_generic_to_shared(&Bs[s][0]);
    }

#define ISSUE_QKV(t, s) do {                                                 \
        int k0_ = (t) * 16;                                                  \
        { int m_ = tid >> 2, kc = tid & 3;                                   \
          const float* src = X + (size_t)(m0 + m_) * 768 + k0_ + kc * 4;     \
          int pred = (m0 + m_ < rows) ? 16 : 0;                              \
          CP16(asm_base[s] + (m_ * AST + kc * 4) * 4, src, pred); }          \
        { int k_ = tid >> 5, cc = tid & 31;                                  \
          const float* src = W + (size_t)(k0_ + k_) * 2304 + c0 + cc * 4;    \
          CP16(bsm_base[s] + (k_ * BST + cc * 4) * 4, src, 16); }            \
        CP_COMMIT();                                                         \
    } while (0)

    ISSUE_QKV(0, 0);
    for (int t = 0; t < 48; t++) {
        int cur = t & 1;
        if (t < 47) { ISSUE_QKV(t + 1, cur ^ 1); CP_WAIT1(); }
        else CP_WAIT0();
        __syncthreads();
        const float* A_ = &As[cur][0];
        const float* B_ = &Bs[cur][0];
#pragma unroll
        for (int kq = 0; kq < 4; kq++) {
            float4 a4[4];
#pragma unroll
            for (int r = 0; r < 4; r++)
                a4[r] = *(const float4*)(A_ + (ty * 4 + r) * AST + kq * 4);
#pragma unroll
            for (int dk = 0; dk < 4; dk++) {
                int k = kq * 4 + dk;
                ulonglong2 b0 = *(const ulonglong2*)(B_ + k * BST + tx * 4);
                ulonglong2 b1 = *(const ulonglong2*)(B_ + k * BST + 64 + tx * 4);
#pragma unroll
                for (int r = 0; r < 4; r++) {
                    float av = (dk == 0) ? a4[r].x : (dk == 1) ? a4[r].y
                             : (dk == 2) ? a4[r].z : a4[r].w;
                    ull ap = pack2s(av);
                    FMA2(acc[r][0], ap, b0.x);
                    FMA2(acc[r][1], ap, b0.y);
                    FMA2(acc[r][2], ap, b1.x);
                    FMA2(acc[r][3], ap, b1.y);
                }
            }
        }
        __syncthreads();
    }
#undef ISSUE_QKV

    float* dq = (which == 0) ? g_tq : (which == 1) ? g_kq : g_cq;
    float* dk_ = (which == 0) ? g_tk : (which == 1) ? g_kk : g_cdk;
    float* dv = (which == 0) ? g_tv : (which == 1) ? g_kv : g_cdv;
#pragma unroll
    for (int r = 0; r < 4; r++) {
        int row = m0 + ty * 4 + r;
        if (row >= rows) continue;
        int b = row / L, n = row % L;
#pragma unroll
        for (int c2 = 0; c2 < 4; c2++) {
            float v0, v1;
            unpack2(acc[r][c2], v0, v1);
#pragma unroll
            for (int u = 0; u < 2; u++) {
                int col = c0 + ((c2 >= 2) ? 64 : 0) + tx * 4 + (c2 & 1) * 2 + u;
                float v = u ? v1 : v0;
                int s = col / 768;
                int rem = col - s * 768;
                int h = rem >> 6, d = rem & 63;
                float* dst = (s == 0) ? dq : (s == 1) ? dk_ : dv;
                dst[((b * Hh + h) * L + n) * Dd + d] = v;
            }
        }
    }
}

// ---------------- merged output projection GEMM (o1 | o2 in one grid) -------
__global__ __launch_bounds__(512, 2) void gemm_proj_kernel(
    const float* __restrict__ W, const float* __restrict__ bias,
    float* __restrict__ o1, float* __restrict__ o2)
{
    __shared__ float As[2][128 * AST];
    __shared__ float Bs[2][16 * BST];
    int by = blockIdx.y;
    const float* A;
    float* O;
    int rows, L, m0;
    if (by < 64) { A = g_att;  O = o1; rows = 8192; L = 2048; m0 = by * 128; }
    else         { A = g_kout; O = o2; rows = 2048; L = 512;  m0 = (by - 64) * 128; }
    int c0 = blockIdx.x * 128;
    int tid = threadIdx.x, tx = tid & 15, ty = tid >> 4;

    ull acc[4][4];
#pragma unroll
    for (int r = 0; r < 4; r++)
#pragma unroll
        for (int c = 0; c < 4; c++) acc[r][c] = 0ull;

    unsigned asm_base[2], bsm_base[2];
#pragma unroll
    for (int s = 0; s < 2; s++) {
        asm_base[s] = (unsigned)__cvta_generic_to_shared(&As[s][0]);
        bsm_base[s] = (unsigned)__cvta_generic_to_shared(&Bs[s][0]);
    }

#define ISSUE_PRJ(t, s) do {                                                  \
        int k0_ = (t) * 16;                                                   \
        { int m_ = tid >> 2, kc = tid & 3;                                    \
          int row = m0 + m_, kg = k0_ + kc * 4;                               \
          int b_ = row / L, n_ = row % L;                                     \
          int h_ = kg >> 6, d_ = kg & 63;                                     \
          const float* src = A + ((size_t)(b_ * Hh + h_) * L + n_) * 64 + d_; \
          CP16(asm_base[s] + (m_ * AST + kc * 4) * 4, src, 16); }             \
        { int k_ = tid >> 5, cc = tid & 31;                                   \
          const float* src = W + (size_t)(k0_ + k_) * 768 + c0 + cc * 4;      \
          CP16(bsm_base[s] + (k_ * BST + cc * 4) * 4, src, 16); }             \
        CP_COMMIT();                                                          \
    } while (0)

    ISSUE_PRJ(0, 0);
    for (int t = 0; t < 48; t++) {
        int cur = t & 1;
        if (t < 47) { ISSUE_PRJ(t + 1, cur ^ 1); CP_WAIT1(); }
        else CP_WAIT0();
        __syncthreads();
        const float* A_ = &As[cur][0];
        const float* B_ = &Bs[cur][0];
#pragma unroll
        for (int kq = 0; kq < 4; kq++) {
            float4 a4[4];
#pragma unroll
            for (int r = 0; r < 4; r++)
                a4[r] = *(const float4*)(A_ + (ty * 4 + r) * AST + kq * 4);
#pragma unroll
            for (int dk = 0; dk < 4; dk++) {
                int k = kq * 4 + dk;
                ulonglong2 b0 = *(const ulonglong2*)(B_ + k * BST + tx * 4);
                ulonglong2 b1 = *(const ulonglong2*)(B_ + k * BST + 64 + tx * 4);
#pragma unroll
                for (int r = 0; r < 4; r++) {
                    float av = (dk == 0) ? a4[r].x : (dk == 1) ? a4[r].y
                             : (dk == 2) ? a4[r].z : a4[r].w;
                    ull ap = pack2s(av);
                    FMA2(acc[r][0], ap, b0.x);
                    FMA2(acc[r][1], ap, b0.y);
                    FMA2(acc[r][2], ap, b1.x);
                    FMA2(acc[r][3], ap, b1.y);
                }
            }
        }
        __syncthreads();
    }
#undef ISSUE_PRJ

#pragma unroll
    for (int r = 0; r < 4; r++) {
        int row = m0 + ty * 4 + r;
#pragma unroll
        for (int c2 = 0; c2 < 4; c2++) {
            float v0, v1;
            unpack2(acc[r][c2], v0, v1);
            int col = c0 + ((c2 >= 2) ? 64 : 0) + tx * 4 + (c2 & 1) * 2;
            O[row * 768 + col]     = v0 + bias[col];
            O[row * 768 + col + 1] = v1 + bias[col + 1];
        }
    }
}

// ---------------- branch 1 (256 thr x 2 CTA/SM, i-tile 32) ------------------
__global__ __launch_bounds__(256, 2) void branch1_kernel(
    const float* __restrict__ krd, float* __restrict__ o4)
{
    extern __shared__ float sm[];
    float* QsT  = sm;                 // 64*34
    float* KT   = QsT + 64 * 34;      // 64*66
    float* Ps   = KT + 64 * 66;       // 64*34
    float* dots = Ps + 64 * 34;       // 32*514
    float* rs1  = dots + 32 * 514;    // 32
    float* rs2  = rs1 + 32;           // 32

    int bh = blockIdx.y;
    int i0 = blockIdx.x * 32;
    int tid = threadIdx.x, tx = tid & 15, ty = tid >> 4;   // ty 0..15
    int w = tid >> 5, lane = tid & 31;                      // 8 warps

    int pd = tid & 63, pj = tid >> 6;   // pj 0..3

    for (int li = tid; li < 2048; li += 256) {
        int d = li & 63, i = li >> 6;
        QsT[d * 34 + i] = g_tq[(bh * Nn + i0 + i) * Dd + d];
    }

    float pf[16];
#pragma unroll
    for (int q = 0; q < 16; q++)
        pf[q] = g_kk[(bh * Mm + (pj + q * 4)) * Dd + pd];

    for (int jt = 0; jt < 8; jt++) {
        int j0 = jt * 64;
        __syncthreads();
#pragma unroll
        for (int q = 0; q < 16; q++)
            KT[pd * 66 + pj + q * 4] = pf[q];
        __syncthreads();
        if (jt < 7) {
#pragma unroll
            for (int q = 0; q < 16; q++)
                pf[q] = g_kk[(bh * Mm + j0 + 64 + pj + q * 4) * Dd + pd];
        }
        ull acc[2][2];
        acc[0][0] = acc[0][1] = acc[1][0] = acc[1][1] = 0ull;
#pragma unroll 16
        for (int k = 0; k < 64; k++) {
            ull aq = *(const ull*)(QsT + k * 34 + ty * 2);
            float af0, af1;
            unpack2(aq, af0, af1);
            ull a0 = pack2s(af0), a1 = pack2s(af1);
            ull b0 = *(const ull*)(KT + k * 66 + tx * 4);
            ull b1 = *(const ull*)(KT + k * 66 + tx * 4 + 2);
            FMA2(acc[0][0], a0, b0); FMA2(acc[0][1], a0, b1);
            FMA2(acc[1][0], a1, b0); FMA2(acc[1][1], a1, b1);
        }
#pragma unroll
        for (int r = 0; r < 2; r++) {
            float v0, v1, v2, v3;
            unpack2(acc[r][0], v0, v1);
            unpack2(acc[r][1], v2, v3);
            float* dp = dots + (ty * 2 + r) * 514 + j0 + tx * 4;
            *(float2*)(dp)     = make_float2(v0 * SCALEc, v1 * SCALEc);
            *(float2*)(dp + 2) = make_float2(v2 * SCALEc, v3 * SCALEc);
        }
    }
    __syncthreads();

    for (int r = 0; r < 4; r++) {
        int i = w * 4 + r;
        const unsigned char* mrow = g_mask + (size_t)(bh * Nn + i0 + i) * Mm;
        float mx = -INFINITY;
        for (int j2 = lane * 2; j2 < 512; j2 += 64) {
            ull dv = *(const ull*)(dots + i * 514 + j2);
            float lo, hi;
            unpack2(dv, lo, hi);
            unsigned short mv = *(const unsigned short*)(mrow + j2);
            if (mv & 0xFFu) lo = NEGc;
            if (mv >> 8)    hi = NEGc;
            *(ull*)(dots + i * 514 + j2) = pack2(lo, hi);
            mx = fmaxf(mx, fmaxf(lo, hi));
        }
#pragma unroll
        for (int o = 16; o; o >>= 1) mx = fmaxf(mx, __shfl_xor_sync(0xffffffffu, mx, o));
        float s1 = 0.f, s2 = 0.f;
        for (int j2 = lane * 2; j2 < 512; j2 += 64) {
            ull dv = *(const ull*)(dots + i * 514 + j2);
            float lo, hi;
            unpack2(dv, lo, hi);
            float e0 = __expf(lo - mx), e1 = __expf(hi - mx);
            ull ep = pack2(e0, e1);
            ull e2p = ep;  MUL2(e2p, e2p);
            ull e4p = e2p; MUL2(e4p, e4p);
            ull e8p = e4p; MUL2(e8p, e8p);
            ull e16p = e8p; MUL2(e16p, e16p);
            ull e24p = e16p; MUL2(e24p, e8p);
            float f24a, f24b;
            unpack2(e24p, f24a, f24b);
            s1 += e0 + e1;
            s2 += f24a + f24b;
            *(ull*)(dots + i * 514 + j2) = ep;
        }
#pragma unroll
        for (int o = 16; o; o >>= 1) {
            s1 += __shfl_xor_sync(0xffffffffu, s1, o);
            s2 += __shfl_xor_sync(0xffffffffu, s2, o);
        }
        if (lane == 0) { rs1[i] = 1.f / s1; rs2[i] = 1.f / s2; }
    }

    float* KV = KT;
    ull acc2[2][2];
    acc2[0][0] = acc2[0][1] = acc2[1][0] = acc2[1][1] = 0ull;

    float pfc[16];
#pragma unroll
    for (int q = 0; q < 16; q++)
        pfc[q] = g_kv[(bh * Mm + (pj + q * 4)) * Dd + pd];

    // krd prefetch for the elementwise pass (4 x float2 per thread)
    ull pkr[4];
#pragma unroll
    for (int s = 0; s < 4; s++) {
        int idx2 = tid + s * 256;
        int jj = idx2 >> 4, ii2 = (idx2 & 15) * 2;
        pkr[s] = *(const ull*)(krd + (size_t)(bh * Mm + jj) * Nn + i0 + ii2);
    }

    for (int jt = 0; jt < 8; jt++) {
        int j0 = jt * 64;
        __syncthreads();
#pragma unroll
        for (int q = 0; q < 16; q++)
            KV[(pj + q * 4) * 66 + pd] = pfc[q];
        if (jt < 7) {
#pragma unroll
            for (int q = 0; q < 16; q++)
                pfc[q] = g_kv[(bh * Mm + j0 + 64 + pj + q * 4) * Dd + pd];
        }
#pragma unroll
        for (int s = 0; s < 4; s++) {
            int idx2 = tid + s * 256;
            int jj = idx2 >> 4, ii2 = (idx2 & 15) * 2;
            float e0 = dots[ii2 * 514 + j0 + jj];
            float e1 = dots[(ii2 + 1) * 514 + j0 + jj];
            ull ep = pack2(e0, e1);
            ull e2p = ep;  MUL2(e2p, e2p);
            ull e4p = e2p; MUL2(e4p, e4p);
            ull e8p = e4p; MUL2(e8p, e8p);
            ull e16p = e8p; MUL2(e16p, e16p);
            ull e24p = e16p; MUL2(e24p, e8p);
            int gi = (bh * Mm + j0 + jj) * Nn + i0 + ii2;
            float k0f, k1f;
            unpack2(pkr[s], k0f, k1f);
            float e24a, e24b;
            unpack2(e24p, e24a, e24b);
            *(float2*)(o4 + gi) = make_float2(e24a * rs2[ii2] * k0f,
                                              e24b * rs2[ii2 + 1] * k1f);
            *(float2*)(Ps + jj * 34 + ii2) = make_float2(e0 * rs1[ii2] * k0f,
                                                         e1 * rs1[ii2 + 1] * k1f);
        }
        __syncthreads();
        // prefetch krd for next tile (covered by the PV loop below)
        if (jt < 7) {
#pragma unroll
            for (int s = 0; s < 4; s++) {
                int idx2 = tid + s * 256;
                int jj = idx2 >> 4, ii2 = (idx2 & 15) * 2;
                pkr[s] = *(const ull*)(krd +
                    (size_t)(bh * Mm + j0 + 64 + jj) * Nn + i0 + ii2);
            }
        }
#pragma unroll 16
        for (int k = 0; k < 64; k++) {
            ull ap = *(const ull*)(Ps + k * 34 + ty * 2);
            float pf0, pf1;
            unpack2(ap, pf0, pf1);
            ull a0 = pack2s(pf0), a1 = pack2s(pf1);
            ull b0 = *(const ull*)(KV + k * 66 + tx * 4);
            ull b1 = *(const ull*)(KV + k * 66 + tx * 4 + 2);
            FMA2(acc2[0][0], a0, b0); FMA2(acc2[0][1], a0, b1);
            FMA2(acc2[1][0], a1, b0); FMA2(acc2[1][1], a1, b1);
        }
    }
#pragma unroll
    for (int r = 0; r < 2; r++) {
        float v0, v1, v2, v3;
        unpack2(acc2[r][0], v0, v1);
        unpack2(acc2[r][1], v2, v3);
        float* op = g_att + (bh * Nn + i0 + ty * 2 + r) * Dd + tx * 4;
        op[0] = v0; op[1] = v1; op[2] = v2; op[3] = v3;
    }
}

// ---------------- branch 2 (512 thr x 2 CTA/SM): k_q vs t_k -----------------
__global__ __launch_bounds__(512, 2) void branch2_kernel(const float* __restrict__ krd)
{
    extern __shared__ float sm[];
    float* QsT = sm;
    float* KsT = QsT + 64 * 68;
    float* Vs  = KsT + 64 * 66;
    float* Ss  = Vs + 64 * 66;
    float* Ps  = Ss + 64 * 66;
    float* mxA = Ps + 64 * 66;
    float* dnA = mxA + 64;
    float* fsc = dnA + 64;

    int bh = blockIdx.y;
    int i0 = blockIdx.x * 64;
    int tid = threadIdx.x, tx = tid & 15, ty = tid >> 4;
    int w = tid >> 5, lane = tid & 31;

    for (int li = tid; li < 4096; li += 512) {
        int d = li & 63, i = li >> 6;
        QsT[d * 68 + i] = g_kq[(bh * Mm + i0 + i) * Dd + d];
    }
    if (tid < 64) { mxA[tid] = -INFINITY; dnA[tid] = 0.f; }

    ull acc[2][2];
    acc[0][0] = acc[0][1] = acc[1][0] = acc[1][1] = 0ull;

    for (int nt = 0; nt < 32; nt++) {
        int n0 = nt * 64;
        __syncthreads();
        for (int li = tid; li < 4096; li += 512) {
            int d = li & 63, j = li >> 6;
            KsT[d * 66 + j] = g_tk[(bh * Nn + n0 + j) * Dd + d];
            Vs[j * 66 + d]  = g_tv[(bh * Nn + n0 + j) * Dd + d];
        }
        __syncthreads();
        {
            ull sac[2][2];
            sac[0][0] = sac[0][1] = sac[1][0] = sac[1][1] = 0ull;
#pragma unroll 16
            for (int k = 0; k < 64; k++) {
                ull aq = *(const ull*)(QsT + k * 68 + ty * 2);
                float af0, af1;
                unpack2(aq, af0, af1);
                ull a0 = pack2s(af0), a1 = pack2s(af1);
                ull b0 = *(const ull*)(KsT + k * 66 + tx * 4);
                ull b1 = *(const ull*)(KsT + k * 66 + tx * 4 + 2);
                FMA2(sac[0][0], a0, b0); FMA2(sac[0][1], a0, b1);
                FMA2(sac[1][0], a1, b0); FMA2(sac[1][1], a1, b1);
            }
#pragma unroll
            for (int r = 0; r < 2; r++) {
                float v0, v1, v2, v3;
                unpack2(sac[r][0], v0, v1);
                unpack2(sac[r][1], v2, v3);
                float* sp = Ss + (ty * 2 + r) * 66 + tx * 4;
                *(float2*)(sp)     = make_float2(v0 * SCALEc, v1 * SCALEc);
                *(float2*)(sp + 2) = make_float2(v2 * SCALEc, v3 * SCALEc);
            }
        }
        __syncthreads();
        for (int idx = tid; idx < 4096; idx += 512) {
            int jj = idx >> 6, ii = idx & 63;
            if (g_mask[(bh * Nn + n0 + jj) * Mm + i0 + ii]) Ss[ii * 66 + jj] = NEGc;
        }
        __syncthreads();
        for (int r = 0; r < 4; r++) {
            int i = w * 4 + r;
            int j2 = lane * 2;
            ull sv = *(const ull*)(Ss + i * 66 + j2);
            float lo, hi;
            unpack2(sv, lo, hi);
            float tmx = fmaxf(lo, hi);
#pragma unroll
            for (int o = 16; o; o >>= 1) tmx = fmaxf(tmx, __shfl_xor_sync(0xffffffffu, tmx, o));
            float om = mxA[i];
            float nm = fmaxf(om, tmx);
            float e0 = __expf(lo - nm), e1 = __expf(hi - nm);
            *(ull*)(Ss + i * 66 + j2) = pack2(e0, e1);
            float s = e0 + e1;
#pragma unroll
            for (int o = 16; o; o >>= 1) s += __shfl_xor_sync(0xffffffffu, s, o);
            if (lane == 0) {
                float f = __expf(om - nm);
                dnA[i] = dnA[i] * f + s;
                mxA[i] = nm;
                fsc[i] = f;
            }
        }
        __syncthreads();
        // P = e * krd: batch the 8 krd loads (MLP=8), then store
        {
            float kr8[8];
#pragma unroll
            for (int s = 0; s < 8; s++) {
                int idx = tid + s * 512;
                int ii = idx >> 6, jj = idx & 63;
                kr8[s] = krd[(size_t)(bh * Mm + i0 + ii) * Nn + n0 + jj];
            }
#pragma unroll
            for (int s = 0; s < 8; s++) {
                int idx = tid + s * 512;
                int ii = idx >> 6, jj = idx & 63;
                Ps[jj * 66 + ii] = Ss[ii * 66 + jj] * kr8[s];
            }
        }
        __syncthreads();
#pragma unroll
        for (int r = 0; r < 2; r++) {
            ull fp = pack2s(fsc[ty * 2 + r]);
            MUL2(acc[r][0], fp);
            MUL2(acc[r][1], fp);
        }
#pragma unroll 16
        for (int k = 0; k < 64; k++) {
            ull ap = *(const ull*)(Ps + k * 66 + ty * 2);
            float pf0, pf1;
            unpack2(ap, pf0, pf1);
            ull a0 = pack2s(pf0), a1 = pack2s(pf1);
            ull b0 = *(const ull*)(Vs + k * 66 + tx * 4);
            ull b1 = *(const ull*)(Vs + k * 66 + tx * 4 + 2);
            FMA2(acc[0][0], a0, b0); FMA2(acc[0][1], a0, b1);
            FMA2(acc[1][0], a1, b0); FMA2(acc[1][1], a1, b1);
        }
    }
    __syncthreads();
#pragma unroll
    for (int r = 0; r < 2; r++) {
        float inv = 1.f / dnA[ty * 2 + r];
        float v0, v1, v2, v3;
        unpack2(acc[r][0], v0, v1);
        unpack2(acc[r][1], v2, v3);
        float* op = g_kout + (bh * Mm + i0 + ty * 2 + r) * Dd + tx * 4;
        op[0] = v0 * inv; op[1] = v1 * inv; op[2] = v2 * inv; op[3] = v3 * inv;
    }
}

// ---------------- branch 3: cluster query (1 per b,h) -----------------------
__global__ __launch_bounds__(256) void branch3_kernel()
{
    __shared__ float cq[64];
    __shared__ float pb[512];
    __shared__ float red[8];
    __shared__ float outp[256];
    __shared__ float smax, ssum;
    int bh = blockIdx.x;
    int b = bh / Hh, h = bh % Hh;
    int tid = threadIdx.x, w = tid >> 5, lane = tid & 31;

    if (tid < 64) cq[tid] = g_cq[bh * Dd + tid];
    __syncthreads();

    for (int j = tid; j < 512; j += 256) {
        float s = 0.f;
#pragma unroll 16
        for (int d = 0; d < 64; d++) s = fmaf(cq[d], g_kk[(bh * Mm + j) * Dd + d], s);
        s *= SCALEc;
        if (g_mask[(size_t)(bh * Nn) * Mm + j]) s = NEGc;
        pb[j] = s;
    }
    __syncthreads();
    float m = -INFINITY;
    for (int j = tid; j < 512; j += 256) m = fmaxf(m, pb[j]);
#pragma unroll
    for (int o = 16; o; o >>= 1) m = fmaxf(m, __shfl_xor_sync(0xffffffffu, m, o));
    if (lane == 0) red[w] = m;
    __syncthreads();
    if (tid == 0) {
        float mm = red[0];
        for (int i = 1; i < 8; i++) mm = fmaxf(mm, red[i]);
        smax = mm;
    }
    __syncthreads();
    float sum = 0.f;
    for (int j = tid; j < 512; j += 256) {
        float e = __expf(pb[j] - smax);
        pb[j] = e;
        sum += e;
    }
#pragma unroll
    for (int o = 16; o; o >>= 1) sum += __shfl_xor_sync(0xffffffffu, sum, o);
    if (lane == 0) red[w] = sum;
    __syncthreads();
    if (tid == 0) {
        float s = 0.f;
        for (int i = 0; i < 8; i++) s += red[i];
        ssum = s;
    }
    __syncthreads();
    int d = tid & 63, q = tid >> 6;
    float a = 0.f;
    for (int j = q * 128; j < (q + 1) * 128; j++)
        a = fmaf(pb[j], g_kv[(bh * Mm + j) * Dd + d], a);
    outp[q * 64 + d] = a;
    __syncthreads();
    if (tid < 64) {
        float tot = outp[tid] + outp[64 + tid] + outp[128 + tid] + outp[192 + tid];
        g_cout[b * DIMc + h * Dd + tid] = tot / ssum;
    }
}

// ---------------- cluster projection ----------------------------------------
__global__ __launch_bounds__(256) void cproj_kernel(
    const float* __restrict__ W, const float* __restrict__ bias,
    float* __restrict__ o3)
{
    int gid = blockIdx.x * 256 + threadIdx.x;  // 3072 total
    int b = gid / 768, c = gid % 768;
    float a = bias[c];
    for (int k = 0; k < 768; k++) a = fmaf(g_cout[b * 768 + k], W[k * 768 + c], a);
    o3[gid] = a;
}

// ---------------- launch ----------------------------------------------------
extern "C" void kernel_launch(void* const* d_in, const int* in_sizes, int n_in,
                              void* d_out, int out_size) {
    const float* x    = (const float*)d_in[0];
    const float* kx   = (const float*)d_in[1];
    const float* krd  = (const float*)d_in[2];
    const float* clst = (const float*)d_in[3];
    const void*  amsk = d_in[4];
    const float* Wqkv = (const float*)d_in[5];
    const float* Wout = (const float*)d_in[6];
    const float* bout = (const float*)d_in[7];
    float* out = (float*)d_out;

    float* o1 = out + O1_OFF;
    float* o2 = out + O2_OFF;
    float* o3 = out + O3_OFF;
    float* o4 = out + O4_OFF;

    size_t sm1 = (size_t)(64*34 + 64*66 + 64*34 + 32*514 + 64) * 4;   // 100,352 B
    size_t sm2 = (size_t)(64*68 + 64*66*4 + 192) * 4;
    cudaFuncSetAttribute(branch1_kernel, cudaFuncAttributeMaxDynamicSharedMemorySize, (int)sm1);
    cudaFuncSetAttribute(branch2_kernel, cudaFuncAttributeMaxDynamicSharedMemorySize, (int)sm2);

    detect_mask_kernel<<<1, 256>>>(amsk);
    norm_mask_kernel<<<MASK_ELEMS / 4 / 256, 256>>>(amsk);

    // merged QKV projection (x | kx | clst)
    gemm_qkv_kernel<<<dim3(18, 81), 512>>>(x, kx, clst, Wqkv);

    // attention branches
    branch1_kernel<<<dim3(64, 48), 256, sm1>>>(krd, o4);
    branch2_kernel<<<dim3(8,  48), 512, sm2>>>(krd);
    branch3_kernel<<<48, 256>>>();

    // merged output projections (o1 | o2)
    gemm_proj_kernel<<<dim3(6, 80), 512>>>(Wout, bout, o1, o2);
    cproj_kernel<<<12, 256>>>(Wout, bout, o3);
}